// round 14
// baseline (speedup 1.0000x reference)
#include <cuda_runtime.h>
#include <cuda_bf16.h>

// Problem constants
#define BB 16
#define NN 25200
#define NC 80
#define STRIDE 85
#define KK 1024
#define MAXDET 1000
#define CONF_T 0.25f
#define IOU_T 0.45f
#define MAXWH 4096.0f

#define NBIN 2048
#define KEY_BASE 0x3E800001u   // smallest float bits > 0.25f
#define GBUF 4096

// ---------------- scratch (device globals; no allocations allowed) --------
__device__ unsigned int        g_key[BB * NN];          // masked conf bits (0 = invalid)
__device__ unsigned char       g_cls[BB * NN];          // argmax class
__device__ int                 g_hist[BB * NBIN];       // per-image key histogram
__device__ float               g_cconf[BB * KK];        // candidate conf (-1 invalid)
__device__ float               g_ccls[BB * KK];         // candidate class (float)
__device__ float4              g_cbox[BB * KK];         // raw xyxy
__device__ float4              g_cobox[BB * KK];        // offset xyxy
__device__ float               g_carea[BB * KK];        // area of offset box
__device__ unsigned long long  g_mask[BB * KK * (KK/64)]; // IoU>thr bitmask (upper block-tri valid)
__device__ int                 g_nvalid[BB];

// ---------------- K0: zero the histograms ---------------------------------
__global__ void zero_hist_kernel() {
    int i = blockIdx.x * blockDim.x + threadIdx.x;
    if (i < BB * NBIN) g_hist[i] = 0;
}

// ---------------- K1: conf/cls per anchor (one warp per anchor) + hist ----
__global__ void score_kernel(const float* __restrict__ pred) {
    int gw   = (blockIdx.x * blockDim.x + threadIdx.x) >> 5;
    int lane = threadIdx.x & 31;
    if (gw >= BB * NN) return;
    const float* p = pred + (size_t)gw * STRIDE;
    float obj = p[4];
    float best = -1.0f; int bi = 0x7fffffff;
    #pragma unroll
    for (int c = lane; c < NC; c += 32) {
        float v = __fmul_rn(p[5 + c], obj); // scores = cls*obj then max (ref order)
        if (v > best) { best = v; bi = c; } // strict > keeps first occurrence
    }
    #pragma unroll
    for (int off = 16; off > 0; off >>= 1) {
        float ov = __shfl_down_sync(0xffffffffu, best, off);
        int   oi = __shfl_down_sync(0xffffffffu, bi,   off);
        if (ov > best || (ov == best && oi < bi)) { best = ov; bi = oi; }
    }
    if (lane == 0) {
        unsigned key = (best > CONF_T) ? __float_as_uint(best) : 0u;
        g_key[gw] = key;
        g_cls[gw] = (unsigned char)bi;
        if (key) {
            unsigned bin = (key - KEY_BASE) >> 13;
            if (bin > (NBIN - 1)) bin = NBIN - 1;
            atomicAdd(&g_hist[(gw / NN) * NBIN + bin], 1);
        }
    }
}

// ---------------- K2: threshold from hist + gather + sort + candidate data -
__global__ void __launch_bounds__(1024) select_sort_kernel(const float* __restrict__ pred) {
    int b = blockIdx.x, tid = threadIdx.x;
    const unsigned* __restrict__ key = g_key + b * NN;

    __shared__ int                s_hist[NBIN];
    __shared__ unsigned long long s_pairs[GBUF];
    __shared__ unsigned           s_T;
    __shared__ int                s_cnt;

    // copy histogram to shared
    for (int i = tid; i < NBIN; i += 1024) s_hist[i] = g_hist[b * NBIN + i];
    if (tid == 0) s_cnt = 0;
    __syncthreads();

    // find threshold bin: largest d with suffix count >= KK (early exit, ~90 iters)
    if (tid == 0) {
        int cum = 0, dstar = 0;
        for (int d = NBIN - 1; d >= 0; --d) {
            cum += s_hist[d];
            if (cum >= KK) { dstar = d; break; }
        }
        s_T = KEY_BASE + ((unsigned)dstar << 13);
    }
    __syncthreads();
    unsigned T = s_T;

    // gather all keys >= T
    for (int a = tid; a < NN; a += 1024) {
        unsigned k = key[a];
        if (k >= T) {
            int p = atomicAdd(&s_cnt, 1);
            if (p < GBUF)
                s_pairs[p] = ((unsigned long long)k << 32) |
                             (unsigned long long)(0xFFFFFFFFu - (unsigned)a);
        }
    }
    __syncthreads();
    int cnt = min(s_cnt, GBUF);
    for (int i = tid; i < GBUF; i += 1024)
        if (i >= cnt) s_pairs[i] = 0ull;

    // bitonic sort GBUF=4096, descending (key desc, idx asc via ~idx)
    for (int k2 = 2; k2 <= GBUF; k2 <<= 1) {
        for (int j = k2 >> 1; j > 0; j >>= 1) {
            __syncthreads();
            for (int idx = tid; idx < GBUF; idx += 1024) {
                int ixj = idx ^ j;
                if (ixj > idx) {
                    bool dir = ((idx & k2) == 0);
                    unsigned long long A = s_pairs[idx], Bv = s_pairs[ixj];
                    if ((A < Bv) == dir) { s_pairs[idx] = Bv; s_pairs[ixj] = A; }
                }
            }
        }
    }
    __syncthreads();

    // candidate data for top-1024 (fused old cand_kernel)
    unsigned long long pr = s_pairs[tid];
    unsigned kk = (unsigned)(pr >> 32);
    unsigned ai = 0xFFFFFFFFu - (unsigned)(pr & 0xFFFFFFFFull);
    int t = b * KK + tid;
    float cx = 0.f, cy = 0.f, w = 0.f, h = 0.f, cls = 0.f;
    if (kk) {
        const float* p = pred + ((size_t)b * NN + (size_t)ai) * STRIDE;
        cx = p[0]; cy = p[1]; w = p[2]; h = p[3];
        cls = (float)g_cls[b * NN + ai];
    }
    float hw = __fmul_rn(w, 0.5f), hh = __fmul_rn(h, 0.5f);
    float x1 = __fsub_rn(cx, hw), y1 = __fsub_rn(cy, hh);
    float x2 = __fadd_rn(cx, hw), y2 = __fadd_rn(cy, hh);
    float off = __fmul_rn(cls, MAXWH);
    float ox1 = __fadd_rn(x1, off), oy1 = __fadd_rn(y1, off);
    float ox2 = __fadd_rn(x2, off), oy2 = __fadd_rn(y2, off);
    g_cbox [t] = make_float4(x1, y1, x2, y2);
    g_cobox[t] = make_float4(ox1, oy1, ox2, oy2);
    g_carea[t] = __fmul_rn(__fsub_rn(ox2, ox1), __fsub_rn(oy2, oy1));
    g_ccls [t] = cls;
    g_cconf[t] = kk ? __uint_as_float(kk) : -1.0f;
    if (tid == 0) g_nvalid[b] = min(cnt, KK);
}

// ---------------- K3: pairwise IoU bitmask, upper block-triangle, ballots --
// grid = BB * 136 blocks of 256 threads; one block per 64x64 tile (cb >= rb)
__global__ void __launch_bounds__(256) iou_kernel() {
    int m = blockIdx.x % 136;
    int b = blockIdx.x / 136;
    // decode m -> (rb, cb) with cb >= rb   (row-major over upper triangle)
    int rb = 0, rem = m;
    #pragma unroll
    for (int i = 0; i < 16; ++i) {
        if (rem >= 16 - rb) { rem -= 16 - rb; rb++; } else break;
    }
    int cb = rb + rem;

    int tid  = threadIdx.x;
    int warp = tid >> 5, lane = tid & 31;

    __shared__ float4 s_box[64];
    __shared__ float  s_area[64];
    if (tid < 64) {
        int c = cb * 64 + tid;
        s_box[tid]  = g_cobox[b * KK + c];
        s_area[tid] = g_carea[b * KK + c];
    }
    __syncthreads();

    #pragma unroll
    for (int k = 0; k < 8; ++k) {
        int row = warp * 8 + k;                 // 0..63 within tile
        int r = rb * 64 + row;
        float4 rbx = g_cobox[b * KK + r];
        float  ra  = g_carea[b * KK + r];

        // column = lane and lane+32
        float4 o0 = s_box[lane];
        float4 o1 = s_box[lane + 32];
        float a0 = s_area[lane], a1 = s_area[lane + 32];

        float ix1 = fmaxf(rbx.x, o0.x), iy1 = fmaxf(rbx.y, o0.y);
        float ix2 = fminf(rbx.z, o0.z), iy2 = fminf(rbx.w, o0.w);
        float iw = fmaxf(__fsub_rn(ix2, ix1), 0.0f);
        float ih = fmaxf(__fsub_rn(iy2, iy1), 0.0f);
        float inter0 = __fmul_rn(iw, ih);
        float den0 = __fadd_rn(__fsub_rn(__fadd_rn(ra, a0), inter0), 1e-9f);
        bool hit0 = __fdiv_rn(inter0, den0) > IOU_T;

        ix1 = fmaxf(rbx.x, o1.x); iy1 = fmaxf(rbx.y, o1.y);
        ix2 = fminf(rbx.z, o1.z); iy2 = fminf(rbx.w, o1.w);
        iw = fmaxf(__fsub_rn(ix2, ix1), 0.0f);
        ih = fmaxf(__fsub_rn(iy2, iy1), 0.0f);
        float inter1 = __fmul_rn(iw, ih);
        float den1 = __fadd_rn(__fsub_rn(__fadd_rn(ra, a1), inter1), 1e-9f);
        bool hit1 = __fdiv_rn(inter1, den1) > IOU_T;

        unsigned lo = __ballot_sync(0xffffffffu, hit0);
        unsigned hi = __ballot_sync(0xffffffffu, hit1);
        if (lane == 0)
            g_mask[((size_t)(b * KK + r)) * (KK/64) + cb] =
                ((unsigned long long)hi << 32) | (unsigned long long)lo;
    }
}

// ---------------- K4: blocked greedy suppression scan + output -----------
__global__ void __launch_bounds__(1024) scan_output_kernel(float* __restrict__ out) {
    int b = blockIdx.x, tid = threadIdx.x;
    const int NW = KK / 64;

    __shared__ unsigned long long s_remv[16];
    __shared__ unsigned long long s_tile[64];
    __shared__ unsigned long long s_keptAll[16];
    __shared__ short              s_outidx[MAXDET];

    int nvalid = g_nvalid[b];
    if (tid < 16) { s_remv[tid] = 0ull; s_keptAll[tid] = 0ull; }
    __syncthreads();

    for (int t = 0; t < 16; ++t) {
        if (tid < 64)
            s_tile[tid] = g_mask[((size_t)(b * KK + t * 64 + tid)) * NW + t];
        __syncthreads();
        if (tid == 0) {
            unsigned long long rem = s_remv[t], kept = 0ull;
            int base = t * 64;
            int lim = nvalid - base; if (lim > 64) lim = 64; if (lim < 0) lim = 0;
            for (int i = 0; i < lim; ++i) {
                if (!((rem >> i) & 1ull)) {
                    kept |= (1ull << i);
                    rem  |= s_tile[i];
                }
            }
            s_keptAll[t] = kept;
        }
        __syncthreads();
        unsigned long long kept = s_keptAll[t];
        int i = tid >> 4, w = tid & 15;
        if (w > t && ((kept >> i) & 1ull))
            atomicOr(&s_remv[w], g_mask[((size_t)(b * KK + t * 64 + i)) * NW + w]);
        __syncthreads();
    }

    // compaction: rank kept candidates (stable order = conf desc already)
    if (tid < MAXDET) s_outidx[tid] = -1;
    __syncthreads();
    {
        int r = tid, wr = r >> 6, br = r & 63;
        unsigned long long kw = s_keptAll[wr];
        if ((kw >> br) & 1ull) {
            int pos = 0;
            for (int w = 0; w < wr; ++w) pos += __popcll(s_keptAll[w]);
            pos += __popcll(kw & ((1ull << br) - 1ull));
            if (pos < MAXDET) s_outidx[pos] = (short)r;
        }
    }
    __syncthreads();

    float* outb = out + (size_t)b * MAXDET * 6;
    for (int row = tid; row < MAXDET; row += 1024) {
        int r = s_outidx[row];
        float v0, v1, v2, v3, v4, v5;
        if (r >= 0) {
            float4 bx = g_cbox[b * KK + r];
            v0 = bx.x; v1 = bx.y; v2 = bx.z; v3 = bx.w;
            v4 = g_cconf[b * KK + r];
            v5 = g_ccls [b * KK + r];
        } else {
            v0 = v1 = v2 = v3 = v4 = v5 = 0.0f;
        }
        float* o = outb + (size_t)row * 6;
        o[0] = v0; o[1] = v1; o[2] = v2; o[3] = v3; o[4] = v4; o[5] = v5;
    }
}

// ---------------- launch ---------------------------------------------------
extern "C" void kernel_launch(void* const* d_in, const int* in_sizes, int n_in,
                              void* d_out, int out_size) {
    const float* pred = (const float*)d_in[0];
    float* out = (float*)d_out;
    (void)in_sizes; (void)n_in; (void)out_size;

    zero_hist_kernel<<<(BB * NBIN + 1023) / 1024, 1024>>>();

    // K1: one warp per anchor, 8 warps/block
    int nblocks1 = (BB * NN + 7) / 8;            // 50400
    score_kernel<<<nblocks1, 256>>>(pred);

    // K2: hist threshold + gather + bitonic sort + candidate data
    select_sort_kernel<<<BB, 1024>>>(pred);

    // K3: IoU mask tiles (upper block triangle)
    iou_kernel<<<BB * 136, 256>>>();

    // K4: suppression scan + output
    scan_output_kernel<<<BB, 1024>>>(out);
}

// round 15
// speedup vs baseline: 1.2449x; 1.2449x over previous
#include <cuda_runtime.h>
#include <cuda_bf16.h>

// Problem constants
#define BB 16
#define NN 25200
#define NC 80
#define STRIDE 85
#define KK 1024
#define MAXDET 1000
#define CONF_T 0.25f
#define IOU_T 0.45f
#define MAXWH 4096.0f

#define NBIN 2048
#define KEY_BASE 0x3E800001u   // smallest float bits > 0.25f
#define GBUF 2048

// ---------------- scratch (device globals; no allocations allowed) --------
__device__ unsigned int        g_key[BB * NN];          // masked conf bits (0 = invalid)
__device__ unsigned char       g_cls[BB * NN];          // argmax class
__device__ int                 g_hist[BB * NBIN];       // per-image key histogram (zeroed by K2)
__device__ float               g_cconf[BB * KK];        // candidate conf (-1 invalid)
__device__ float               g_ccls[BB * KK];         // candidate class (float)
__device__ float4              g_cbox[BB * KK];         // raw xyxy
__device__ float4              g_cobox[BB * KK];        // offset xyxy
__device__ float               g_carea[BB * KK];        // area of offset box
__device__ unsigned long long  g_mask[BB * KK * (KK/64)]; // IoU>thr bitmask (upper block-tri valid)
__device__ int                 g_nvalid[BB];

// ---------------- K1: conf/cls per anchor (one warp per anchor) + hist ----
__global__ void score_kernel(const float* __restrict__ pred) {
    int gw   = (blockIdx.x * blockDim.x + threadIdx.x) >> 5;
    int lane = threadIdx.x & 31;
    if (gw >= BB * NN) return;
    const float* p = pred + (size_t)gw * STRIDE;
    float obj = p[4];
    float best = -1.0f; int bi = 0x7fffffff;
    #pragma unroll
    for (int c = lane; c < NC; c += 32) {
        float v = __fmul_rn(p[5 + c], obj); // scores = cls*obj then max (ref order)
        if (v > best) { best = v; bi = c; } // strict > keeps first occurrence
    }
    #pragma unroll
    for (int off = 16; off > 0; off >>= 1) {
        float ov = __shfl_down_sync(0xffffffffu, best, off);
        int   oi = __shfl_down_sync(0xffffffffu, bi,   off);
        if (ov > best || (ov == best && oi < bi)) { best = ov; bi = oi; }
    }
    if (lane == 0) {
        unsigned key = (best > CONF_T) ? __float_as_uint(best) : 0u;
        g_key[gw] = key;
        g_cls[gw] = (unsigned char)bi;
        if (key) {
            unsigned bin = (key - KEY_BASE) >> 13;
            if (bin > (NBIN - 1)) bin = NBIN - 1;
            atomicAdd(&g_hist[(gw / NN) * NBIN + bin], 1);
        }
    }
}

// ---------------- K2: threshold from hist + gather + sort + candidate data -
__global__ void __launch_bounds__(1024) select_sort_kernel(const float* __restrict__ pred) {
    int b = blockIdx.x, tid = threadIdx.x;
    const unsigned* __restrict__ key = g_key + b * NN;

    __shared__ int                s_hist[NBIN];
    __shared__ int                s_chunk[64];
    __shared__ unsigned long long s_pairs[GBUF];
    __shared__ unsigned           s_T;
    __shared__ int                s_cnt;

    // copy histogram to shared, zero global copy for the next run
    for (int i = tid; i < NBIN; i += 1024) {
        s_hist[i] = g_hist[b * NBIN + i];
        g_hist[b * NBIN + i] = 0;
    }
    if (tid == 0) s_cnt = 0;
    __syncthreads();

    // 2-level threshold search: 64 chunk sums, then <=96 serial steps
    if (tid < 64) {
        int s = 0;
        #pragma unroll
        for (int i = 0; i < 32; ++i) s += s_hist[tid * 32 + i];
        s_chunk[tid] = s;
    }
    __syncthreads();
    if (tid == 0) {
        int cum = 0, dstar = 0;
        for (int c = 63; c >= 0; --c) {
            int cs = s_chunk[c];
            if (cum + cs >= KK) {
                for (int d = c * 32 + 31; d >= c * 32; --d) {
                    cum += s_hist[d];
                    if (cum >= KK) { dstar = d; break; }
                }
                break;
            }
            cum += cs;
        }
        s_T = KEY_BASE + ((unsigned)dstar << 13);
    }
    __syncthreads();
    unsigned T = s_T;

    // gather all keys >= T  (count ~ KK + few; GBUF=2048 ample)
    for (int a = tid; a < NN; a += 1024) {
        unsigned k = key[a];
        if (k >= T) {
            int p = atomicAdd(&s_cnt, 1);
            if (p < GBUF)
                s_pairs[p] = ((unsigned long long)k << 32) |
                             (unsigned long long)(0xFFFFFFFFu - (unsigned)a);
        }
    }
    __syncthreads();
    int cnt = min(s_cnt, GBUF);
    for (int i = tid; i < GBUF; i += 1024)
        if (i >= cnt) s_pairs[i] = 0ull;

    // bitonic sort GBUF=2048, descending (key desc, idx asc via ~idx)
    for (int k2 = 2; k2 <= GBUF; k2 <<= 1) {
        for (int j = k2 >> 1; j > 0; j >>= 1) {
            __syncthreads();
            for (int idx = tid; idx < GBUF; idx += 1024) {
                int ixj = idx ^ j;
                if (ixj > idx) {
                    bool dir = ((idx & k2) == 0);
                    unsigned long long A = s_pairs[idx], Bv = s_pairs[ixj];
                    if ((A < Bv) == dir) { s_pairs[idx] = Bv; s_pairs[ixj] = A; }
                }
            }
        }
    }
    __syncthreads();

    // candidate data for top-1024 (fused gather of boxes/areas/classes)
    unsigned long long pr = s_pairs[tid];
    unsigned kk = (unsigned)(pr >> 32);
    unsigned ai = 0xFFFFFFFFu - (unsigned)(pr & 0xFFFFFFFFull);
    int t = b * KK + tid;
    float cx = 0.f, cy = 0.f, w = 0.f, h = 0.f, cls = 0.f;
    if (kk) {
        const float* p = pred + ((size_t)b * NN + (size_t)ai) * STRIDE;
        cx = p[0]; cy = p[1]; w = p[2]; h = p[3];
        cls = (float)g_cls[b * NN + ai];
    }
    float hw = __fmul_rn(w, 0.5f), hh = __fmul_rn(h, 0.5f);
    float x1 = __fsub_rn(cx, hw), y1 = __fsub_rn(cy, hh);
    float x2 = __fadd_rn(cx, hw), y2 = __fadd_rn(cy, hh);
    float off = __fmul_rn(cls, MAXWH);
    float ox1 = __fadd_rn(x1, off), oy1 = __fadd_rn(y1, off);
    float ox2 = __fadd_rn(x2, off), oy2 = __fadd_rn(y2, off);
    g_cbox [t] = make_float4(x1, y1, x2, y2);
    g_cobox[t] = make_float4(ox1, oy1, ox2, oy2);
    g_carea[t] = __fmul_rn(__fsub_rn(ox2, ox1), __fsub_rn(oy2, oy1));
    g_ccls [t] = cls;
    g_cconf[t] = kk ? __uint_as_float(kk) : -1.0f;
    if (tid == 0) g_nvalid[b] = min(cnt, KK);
}

// ---------------- K3: pairwise IoU bitmask, upper block-triangle, ballots --
// grid = BB * 136 blocks of 256 threads; one block per 64x64 tile (cb >= rb)
// Division is guarded by inter > 0: when inter == 0, iou == 0 exactly (0/den),
// so hit=false is bitwise identical — and ~99% of pairs never touch the div.
__global__ void __launch_bounds__(256) iou_kernel() {
    int m = blockIdx.x % 136;
    int b = blockIdx.x / 136;
    int rb = 0, rem = m;
    #pragma unroll
    for (int i = 0; i < 16; ++i) {
        if (rem >= 16 - rb) { rem -= 16 - rb; rb++; } else break;
    }
    int cb = rb + rem;

    int tid  = threadIdx.x;
    int warp = tid >> 5, lane = tid & 31;

    __shared__ float4 s_box[64];
    __shared__ float  s_area[64];
    if (tid < 64) {
        int c = cb * 64 + tid;
        s_box[tid]  = g_cobox[b * KK + c];
        s_area[tid] = g_carea[b * KK + c];
    }
    __syncthreads();

    #pragma unroll
    for (int k = 0; k < 8; ++k) {
        int row = warp * 8 + k;                 // 0..63 within tile
        int r = rb * 64 + row;
        float4 rbx = g_cobox[b * KK + r];
        float  ra  = g_carea[b * KK + r];

        float4 o0 = s_box[lane];
        float4 o1 = s_box[lane + 32];

        float ix1 = fmaxf(rbx.x, o0.x), iy1 = fmaxf(rbx.y, o0.y);
        float ix2 = fminf(rbx.z, o0.z), iy2 = fminf(rbx.w, o0.w);
        float iw = fmaxf(__fsub_rn(ix2, ix1), 0.0f);
        float ih = fmaxf(__fsub_rn(iy2, iy1), 0.0f);
        float inter0 = __fmul_rn(iw, ih);

        ix1 = fmaxf(rbx.x, o1.x); iy1 = fmaxf(rbx.y, o1.y);
        ix2 = fminf(rbx.z, o1.z); iy2 = fminf(rbx.w, o1.w);
        iw = fmaxf(__fsub_rn(ix2, ix1), 0.0f);
        ih = fmaxf(__fsub_rn(iy2, iy1), 0.0f);
        float inter1 = __fmul_rn(iw, ih);

        bool hit0 = false, hit1 = false;
        if (inter0 > 0.0f) {
            float den0 = __fadd_rn(__fsub_rn(__fadd_rn(ra, s_area[lane]), inter0), 1e-9f);
            hit0 = __fdiv_rn(inter0, den0) > IOU_T;
        }
        if (inter1 > 0.0f) {
            float den1 = __fadd_rn(__fsub_rn(__fadd_rn(ra, s_area[lane + 32]), inter1), 1e-9f);
            hit1 = __fdiv_rn(inter1, den1) > IOU_T;
        }

        unsigned lo = __ballot_sync(0xffffffffu, hit0);
        unsigned hi = __ballot_sync(0xffffffffu, hit1);
        if (lane == 0)
            g_mask[((size_t)(b * KK + r)) * (KK/64) + cb] =
                ((unsigned long long)hi << 32) | (unsigned long long)lo;
    }
}

// ---------------- K4: blocked greedy suppression scan + output -----------
__global__ void __launch_bounds__(1024) scan_output_kernel(float* __restrict__ out) {
    int b = blockIdx.x, tid = threadIdx.x;
    const int NW = KK / 64;

    __shared__ unsigned long long s_remv[16];
    __shared__ unsigned long long s_tile[64];
    __shared__ unsigned long long s_keptAll[16];
    __shared__ short              s_outidx[MAXDET];

    int nvalid = g_nvalid[b];
    if (tid < 16) { s_remv[tid] = 0ull; s_keptAll[tid] = 0ull; }
    __syncthreads();

    for (int t = 0; t < 16; ++t) {
        if (tid < 64)
            s_tile[tid] = g_mask[((size_t)(b * KK + t * 64 + tid)) * NW + t];
        __syncthreads();
        if (tid == 0) {
            unsigned long long rem = s_remv[t], kept = 0ull;
            int base = t * 64;
            int lim = nvalid - base; if (lim > 64) lim = 64; if (lim < 0) lim = 0;
            for (int i = 0; i < lim; ++i) {
                if (!((rem >> i) & 1ull)) {
                    kept |= (1ull << i);
                    rem  |= s_tile[i];
                }
            }
            s_keptAll[t] = kept;
        }
        __syncthreads();
        unsigned long long kept = s_keptAll[t];
        int i = tid >> 4, w = tid & 15;
        if (w > t && ((kept >> i) & 1ull))
            atomicOr(&s_remv[w], g_mask[((size_t)(b * KK + t * 64 + i)) * NW + w]);
        __syncthreads();
    }

    // compaction: rank kept candidates (stable order = conf desc already)
    if (tid < MAXDET) s_outidx[tid] = -1;
    __syncthreads();
    {
        int r = tid, wr = r >> 6, br = r & 63;
        unsigned long long kw = s_keptAll[wr];
        if ((kw >> br) & 1ull) {
            int pos = 0;
            for (int w = 0; w < wr; ++w) pos += __popcll(s_keptAll[w]);
            pos += __popcll(kw & ((1ull << br) - 1ull));
            if (pos < MAXDET) s_outidx[pos] = (short)r;
        }
    }
    __syncthreads();

    float* outb = out + (size_t)b * MAXDET * 6;
    for (int row = tid; row < MAXDET; row += 1024) {
        int r = s_outidx[row];
        float v0, v1, v2, v3, v4, v5;
        if (r >= 0) {
            float4 bx = g_cbox[b * KK + r];
            v0 = bx.x; v1 = bx.y; v2 = bx.z; v3 = bx.w;
            v4 = g_cconf[b * KK + r];
            v5 = g_ccls [b * KK + r];
        } else {
            v0 = v1 = v2 = v3 = v4 = v5 = 0.0f;
        }
        float* o = outb + (size_t)row * 6;
        o[0] = v0; o[1] = v1; o[2] = v2; o[3] = v3; o[4] = v4; o[5] = v5;
    }
}

// ---------------- launch ---------------------------------------------------
extern "C" void kernel_launch(void* const* d_in, const int* in_sizes, int n_in,
                              void* d_out, int out_size) {
    const float* pred = (const float*)d_in[0];
    float* out = (float*)d_out;
    (void)in_sizes; (void)n_in; (void)out_size;

    // K1: one warp per anchor, 8 warps/block (g_hist is zero at entry:
    // zero-initialized at load, re-zeroed by select_sort each run)
    int nblocks1 = (BB * NN + 7) / 8;            // 50400
    score_kernel<<<nblocks1, 256>>>(pred);

    // K2: hist threshold + gather + bitonic sort + candidate data
    select_sort_kernel<<<BB, 1024>>>(pred);

    // K3: IoU mask tiles (upper block triangle)
    iou_kernel<<<BB * 136, 256>>>();

    // K4: suppression scan + output
    scan_output_kernel<<<BB, 1024>>>(out);
}

// round 16
// speedup vs baseline: 1.2468x; 1.0016x over previous
#include <cuda_runtime.h>
#include <cuda_bf16.h>

// Problem constants
#define BB 16
#define NN 25200
#define NC 80
#define STRIDE 85
#define KK 1024
#define MAXDET 1000
#define CONF_T 0.25f
#define IOU_T 0.45f
#define MAXWH 4096.0f

#define NBIN 2048
#define KEY_BASE 0x3E800001u   // smallest float bits > 0.25f
#define GBUF 2048

// ---------------- scratch (device globals; no allocations allowed) --------
__device__ unsigned int        g_key[BB * NN];          // masked conf bits (0 = invalid)
__device__ unsigned char       g_cls[BB * NN];          // argmax class
__device__ int                 g_hist[BB * NBIN];       // per-image key histogram (zeroed by K2)
__device__ float               g_cconf[BB * KK];        // candidate conf (-1 invalid)
__device__ float               g_ccls[BB * KK];         // candidate class (float)
__device__ float4              g_cbox[BB * KK];         // raw xyxy
__device__ float4              g_cobox[BB * KK];        // offset xyxy
__device__ float               g_carea[BB * KK];        // area of offset box
__device__ unsigned long long  g_mask[BB * KK * (KK/64)]; // IoU>thr bitmask (upper block-tri valid)
__device__ int                 g_nvalid[BB];

// ---------------- K1: conf/cls per anchor (one warp per anchor) + hist ----
__global__ void score_kernel(const float* __restrict__ pred) {
    int gw   = (blockIdx.x * blockDim.x + threadIdx.x) >> 5;
    int lane = threadIdx.x & 31;
    if (gw >= BB * NN) return;
    const float* p = pred + (size_t)gw * STRIDE;
    float obj = p[4];
    float best = -1.0f; int bi = 0x7fffffff;
    #pragma unroll
    for (int c = lane; c < NC; c += 32) {
        float v = __fmul_rn(p[5 + c], obj); // scores = cls*obj then max (ref order)
        if (v > best) { best = v; bi = c; } // strict > keeps first occurrence
    }
    #pragma unroll
    for (int off = 16; off > 0; off >>= 1) {
        float ov = __shfl_down_sync(0xffffffffu, best, off);
        int   oi = __shfl_down_sync(0xffffffffu, bi,   off);
        if (ov > best || (ov == best && oi < bi)) { best = ov; bi = oi; }
    }
    if (lane == 0) {
        unsigned key = (best > CONF_T) ? __float_as_uint(best) : 0u;
        g_key[gw] = key;
        g_cls[gw] = (unsigned char)bi;
        if (key) {
            unsigned bin = (key - KEY_BASE) >> 13;
            if (bin > (NBIN - 1)) bin = NBIN - 1;
            atomicAdd(&g_hist[(gw / NN) * NBIN + bin], 1);
        }
    }
}

// ---------------- K2: threshold from hist + gather + sort + candidate data -
__global__ void __launch_bounds__(1024) select_sort_kernel(const float* __restrict__ pred) {
    int b = blockIdx.x, tid = threadIdx.x;
    const unsigned* __restrict__ key = g_key + b * NN;

    __shared__ int                s_hist[NBIN];
    __shared__ int                s_chunk[64];
    __shared__ unsigned long long s_pairs[GBUF];
    __shared__ unsigned           s_T;
    __shared__ int                s_cnt;

    // copy histogram to shared, zero global copy for the next run
    for (int i = tid; i < NBIN; i += 1024) {
        s_hist[i] = g_hist[b * NBIN + i];
        g_hist[b * NBIN + i] = 0;
    }
    if (tid == 0) s_cnt = 0;
    __syncthreads();

    // 2-level threshold search: 64 chunk sums, then <=96 serial steps
    if (tid < 64) {
        int s = 0;
        #pragma unroll
        for (int i = 0; i < 32; ++i) s += s_hist[tid * 32 + i];
        s_chunk[tid] = s;
    }
    __syncthreads();
    if (tid == 0) {
        int cum = 0, dstar = 0;
        for (int c = 63; c >= 0; --c) {
            int cs = s_chunk[c];
            if (cum + cs >= KK) {
                for (int d = c * 32 + 31; d >= c * 32; --d) {
                    cum += s_hist[d];
                    if (cum >= KK) { dstar = d; break; }
                }
                break;
            }
            cum += cs;
        }
        s_T = KEY_BASE + ((unsigned)dstar << 13);
    }
    __syncthreads();
    unsigned T = s_T;

    // gather all keys >= T  (count ~ KK + few; GBUF=2048 ample)
    for (int a = tid; a < NN; a += 1024) {
        unsigned k = key[a];
        if (k >= T) {
            int p = atomicAdd(&s_cnt, 1);
            if (p < GBUF)
                s_pairs[p] = ((unsigned long long)k << 32) |
                             (unsigned long long)(0xFFFFFFFFu - (unsigned)a);
        }
    }
    __syncthreads();
    int cnt = min(s_cnt, GBUF);
    for (int i = tid; i < GBUF; i += 1024)
        if (i >= cnt) s_pairs[i] = 0ull;

    // bitonic sort GBUF=2048, descending (key desc, idx asc via ~idx)
    for (int k2 = 2; k2 <= GBUF; k2 <<= 1) {
        for (int j = k2 >> 1; j > 0; j >>= 1) {
            __syncthreads();
            for (int idx = tid; idx < GBUF; idx += 1024) {
                int ixj = idx ^ j;
                if (ixj > idx) {
                    bool dir = ((idx & k2) == 0);
                    unsigned long long A = s_pairs[idx], Bv = s_pairs[ixj];
                    if ((A < Bv) == dir) { s_pairs[idx] = Bv; s_pairs[ixj] = A; }
                }
            }
        }
    }
    __syncthreads();

    // candidate data for top-1024 (fused gather of boxes/areas/classes)
    unsigned long long pr = s_pairs[tid];
    unsigned kk = (unsigned)(pr >> 32);
    unsigned ai = 0xFFFFFFFFu - (unsigned)(pr & 0xFFFFFFFFull);
    int t = b * KK + tid;
    float cx = 0.f, cy = 0.f, w = 0.f, h = 0.f, cls = 0.f;
    if (kk) {
        const float* p = pred + ((size_t)b * NN + (size_t)ai) * STRIDE;
        cx = p[0]; cy = p[1]; w = p[2]; h = p[3];
        cls = (float)g_cls[b * NN + ai];
    }
    float hw = __fmul_rn(w, 0.5f), hh = __fmul_rn(h, 0.5f);
    float x1 = __fsub_rn(cx, hw), y1 = __fsub_rn(cy, hh);
    float x2 = __fadd_rn(cx, hw), y2 = __fadd_rn(cy, hh);
    float off = __fmul_rn(cls, MAXWH);
    float ox1 = __fadd_rn(x1, off), oy1 = __fadd_rn(y1, off);
    float ox2 = __fadd_rn(x2, off), oy2 = __fadd_rn(y2, off);
    g_cbox [t] = make_float4(x1, y1, x2, y2);
    g_cobox[t] = make_float4(ox1, oy1, ox2, oy2);
    g_carea[t] = __fmul_rn(__fsub_rn(ox2, ox1), __fsub_rn(oy2, oy1));
    g_ccls [t] = cls;
    g_cconf[t] = kk ? __uint_as_float(kk) : -1.0f;
    if (tid == 0) g_nvalid[b] = min(cnt, KK);
}

// ---------------- K3: pairwise IoU bitmask, upper block-triangle, ballots --
// grid = BB * 136 blocks of 256 threads; one block per 64x64 tile (cb >= rb)
// Division is guarded by inter > 0: when inter == 0, iou == 0 exactly (0/den),
// so hit=false is bitwise identical — and ~99% of pairs never touch the div.
__global__ void __launch_bounds__(256) iou_kernel() {
    int m = blockIdx.x % 136;
    int b = blockIdx.x / 136;
    int rb = 0, rem = m;
    #pragma unroll
    for (int i = 0; i < 16; ++i) {
        if (rem >= 16 - rb) { rem -= 16 - rb; rb++; } else break;
    }
    int cb = rb + rem;

    int tid  = threadIdx.x;
    int warp = tid >> 5, lane = tid & 31;

    __shared__ float4 s_box[64];
    __shared__ float  s_area[64];
    if (tid < 64) {
        int c = cb * 64 + tid;
        s_box[tid]  = g_cobox[b * KK + c];
        s_area[tid] = g_carea[b * KK + c];
    }
    __syncthreads();

    #pragma unroll
    for (int k = 0; k < 8; ++k) {
        int row = warp * 8 + k;                 // 0..63 within tile
        int r = rb * 64 + row;
        float4 rbx = g_cobox[b * KK + r];
        float  ra  = g_carea[b * KK + r];

        float4 o0 = s_box[lane];
        float4 o1 = s_box[lane + 32];

        float ix1 = fmaxf(rbx.x, o0.x), iy1 = fmaxf(rbx.y, o0.y);
        float ix2 = fminf(rbx.z, o0.z), iy2 = fminf(rbx.w, o0.w);
        float iw = fmaxf(__fsub_rn(ix2, ix1), 0.0f);
        float ih = fmaxf(__fsub_rn(iy2, iy1), 0.0f);
        float inter0 = __fmul_rn(iw, ih);

        ix1 = fmaxf(rbx.x, o1.x); iy1 = fmaxf(rbx.y, o1.y);
        ix2 = fminf(rbx.z, o1.z); iy2 = fminf(rbx.w, o1.w);
        iw = fmaxf(__fsub_rn(ix2, ix1), 0.0f);
        ih = fmaxf(__fsub_rn(iy2, iy1), 0.0f);
        float inter1 = __fmul_rn(iw, ih);

        bool hit0 = false, hit1 = false;
        if (inter0 > 0.0f) {
            float den0 = __fadd_rn(__fsub_rn(__fadd_rn(ra, s_area[lane]), inter0), 1e-9f);
            hit0 = __fdiv_rn(inter0, den0) > IOU_T;
        }
        if (inter1 > 0.0f) {
            float den1 = __fadd_rn(__fsub_rn(__fadd_rn(ra, s_area[lane + 32]), inter1), 1e-9f);
            hit1 = __fdiv_rn(inter1, den1) > IOU_T;
        }

        unsigned lo = __ballot_sync(0xffffffffu, hit0);
        unsigned hi = __ballot_sync(0xffffffffu, hit1);
        if (lane == 0)
            g_mask[((size_t)(b * KK + r)) * (KK/64) + cb] =
                ((unsigned long long)hi << 32) | (unsigned long long)lo;
    }
}

// ---------------- K4: blocked greedy suppression scan + output -----------
__global__ void __launch_bounds__(1024) scan_output_kernel(float* __restrict__ out) {
    int b = blockIdx.x, tid = threadIdx.x;
    const int NW = KK / 64;

    __shared__ unsigned long long s_remv[16];
    __shared__ unsigned long long s_tile[64];
    __shared__ unsigned long long s_keptAll[16];
    __shared__ short              s_outidx[MAXDET];

    int nvalid = g_nvalid[b];
    if (tid < 16) { s_remv[tid] = 0ull; s_keptAll[tid] = 0ull; }
    __syncthreads();

    for (int t = 0; t < 16; ++t) {
        if (tid < 64)
            s_tile[tid] = g_mask[((size_t)(b * KK + t * 64 + tid)) * NW + t];
        __syncthreads();
        if (tid == 0) {
            unsigned long long rem = s_remv[t], kept = 0ull;
            int base = t * 64;
            int lim = nvalid - base; if (lim > 64) lim = 64; if (lim < 0) lim = 0;
            for (int i = 0; i < lim; ++i) {
                if (!((rem >> i) & 1ull)) {
                    kept |= (1ull << i);
                    rem  |= s_tile[i];
                }
            }
            s_keptAll[t] = kept;
        }
        __syncthreads();
        unsigned long long kept = s_keptAll[t];
        int i = tid >> 4, w = tid & 15;
        if (w > t && ((kept >> i) & 1ull))
            atomicOr(&s_remv[w], g_mask[((size_t)(b * KK + t * 64 + i)) * NW + w]);
        __syncthreads();
    }

    // compaction: rank kept candidates (stable order = conf desc already)
    if (tid < MAXDET) s_outidx[tid] = -1;
    __syncthreads();
    {
        int r = tid, wr = r >> 6, br = r & 63;
        unsigned long long kw = s_keptAll[wr];
        if ((kw >> br) & 1ull) {
            int pos = 0;
            for (int w = 0; w < wr; ++w) pos += __popcll(s_keptAll[w]);
            pos += __popcll(kw & ((1ull << br) - 1ull));
            if (pos < MAXDET) s_outidx[pos] = (short)r;
        }
    }
    __syncthreads();

    float* outb = out + (size_t)b * MAXDET * 6;
    for (int row = tid; row < MAXDET; row += 1024) {
        int r = s_outidx[row];
        float v0, v1, v2, v3, v4, v5;
        if (r >= 0) {
            float4 bx = g_cbox[b * KK + r];
            v0 = bx.x; v1 = bx.y; v2 = bx.z; v3 = bx.w;
            v4 = g_cconf[b * KK + r];
            v5 = g_ccls [b * KK + r];
        } else {
            v0 = v1 = v2 = v3 = v4 = v5 = 0.0f;
        }
        float* o = outb + (size_t)row * 6;
        o[0] = v0; o[1] = v1; o[2] = v2; o[3] = v3; o[4] = v4; o[5] = v5;
    }
}

// ---------------- launch ---------------------------------------------------
extern "C" void kernel_launch(void* const* d_in, const int* in_sizes, int n_in,
                              void* d_out, int out_size) {
    const float* pred = (const float*)d_in[0];
    float* out = (float*)d_out;
    (void)in_sizes; (void)n_in; (void)out_size;

    // K1: one warp per anchor, 8 warps/block (g_hist is zero at entry:
    // zero-initialized at load, re-zeroed by select_sort each run)
    int nblocks1 = (BB * NN + 7) / 8;            // 50400
    score_kernel<<<nblocks1, 256>>>(pred);

    // K2: hist threshold + gather + bitonic sort + candidate data
    select_sort_kernel<<<BB, 1024>>>(pred);

    // K3: IoU mask tiles (upper block triangle)
    iou_kernel<<<BB * 136, 256>>>();

    // K4: suppression scan + output
    scan_output_kernel<<<BB, 1024>>>(out);
}

// round 17
// speedup vs baseline: 1.3432x; 1.0773x over previous
#include <cuda_runtime.h>
#include <cuda_bf16.h>

// Problem constants
#define BB 16
#define NN 25200
#define NC 80
#define STRIDE 85
#define KK 1024
#define MAXDET 1000
#define CONF_T 0.25f
#define IOU_T 0.45f
#define MAXWH 4096.0f

#define NBIN 2048
#define KEY_BASE 0x3E800001u   // smallest float bits > 0.25f
#define GBUF 2048

// ---------------- scratch (device globals; no allocations allowed) --------
__device__ unsigned int        g_key[BB * NN];          // masked conf bits (0 = invalid)
__device__ unsigned char       g_cls[BB * NN];          // argmax class
__device__ int                 g_hist[BB * NBIN];       // per-image key histogram (zeroed by K2)
__device__ float               g_cconf[BB * KK];        // candidate conf (-1 invalid)
__device__ float               g_ccls[BB * KK];         // candidate class (float)
__device__ float4              g_cbox[BB * KK];         // raw xyxy
__device__ float4              g_cobox[BB * KK];        // offset xyxy
__device__ float               g_carea[BB * KK];        // area of offset box
__device__ unsigned long long  g_mask[BB * KK * (KK/64)]; // IoU>thr bitmask (upper block-tri valid)
__device__ int                 g_nvalid[BB];

// ---------------- K1: conf/cls per anchor (one warp per anchor) + hist ----
__global__ void score_kernel(const float* __restrict__ pred) {
    int gw   = (blockIdx.x * blockDim.x + threadIdx.x) >> 5;
    int lane = threadIdx.x & 31;
    if (gw >= BB * NN) return;
    const float* p = pred + (size_t)gw * STRIDE;
    float obj = p[4];
    float best = -1.0f; int bi = 0x7fffffff;
    #pragma unroll
    for (int c = lane; c < NC; c += 32) {
        float v = __fmul_rn(p[5 + c], obj); // scores = cls*obj then max (ref order)
        if (v > best) { best = v; bi = c; } // strict > keeps first occurrence
    }
    #pragma unroll
    for (int off = 16; off > 0; off >>= 1) {
        float ov = __shfl_down_sync(0xffffffffu, best, off);
        int   oi = __shfl_down_sync(0xffffffffu, bi,   off);
        if (ov > best || (ov == best && oi < bi)) { best = ov; bi = oi; }
    }
    if (lane == 0) {
        unsigned key = (best > CONF_T) ? __float_as_uint(best) : 0u;
        g_key[gw] = key;
        g_cls[gw] = (unsigned char)bi;
        if (key) {
            unsigned bin = (key - KEY_BASE) >> 13;
            if (bin > (NBIN - 1)) bin = NBIN - 1;
            atomicAdd(&g_hist[(gw / NN) * NBIN + bin], 1);
        }
    }
}

// ---------------- K2: threshold from hist + gather + sort + candidate data -
__global__ void __launch_bounds__(1024) select_sort_kernel(const float* __restrict__ pred) {
    int b = blockIdx.x, tid = threadIdx.x;
    const unsigned* __restrict__ key = g_key + b * NN;

    __shared__ int                s_hist[NBIN];
    __shared__ int                s_chunk[64];
    __shared__ unsigned long long s_pairs[GBUF];
    __shared__ unsigned           s_T;
    __shared__ int                s_cnt;

    // copy histogram to shared, zero global copy for the next run
    for (int i = tid; i < NBIN; i += 1024) {
        s_hist[i] = g_hist[b * NBIN + i];
        g_hist[b * NBIN + i] = 0;
    }
    if (tid == 0) s_cnt = 0;
    __syncthreads();

    // 2-level threshold search: 64 chunk sums, then <=96 serial steps
    if (tid < 64) {
        int s = 0;
        #pragma unroll
        for (int i = 0; i < 32; ++i) s += s_hist[tid * 32 + i];
        s_chunk[tid] = s;
    }
    __syncthreads();
    if (tid == 0) {
        int cum = 0, dstar = 0;
        for (int c = 63; c >= 0; --c) {
            int cs = s_chunk[c];
            if (cum + cs >= KK) {
                for (int d = c * 32 + 31; d >= c * 32; --d) {
                    cum += s_hist[d];
                    if (cum >= KK) { dstar = d; break; }
                }
                break;
            }
            cum += cs;
        }
        s_T = KEY_BASE + ((unsigned)dstar << 13);
    }
    __syncthreads();
    unsigned T = s_T;

    // gather all keys >= T  (count ~ KK + few; GBUF=2048 ample)
    for (int a = tid; a < NN; a += 1024) {
        unsigned k = key[a];
        if (k >= T) {
            int p = atomicAdd(&s_cnt, 1);
            if (p < GBUF)
                s_pairs[p] = ((unsigned long long)k << 32) |
                             (unsigned long long)(0xFFFFFFFFu - (unsigned)a);
        }
    }
    __syncthreads();
    int cnt = min(s_cnt, GBUF);
    for (int i = tid; i < GBUF; i += 1024)
        if (i >= cnt) s_pairs[i] = 0ull;

    // bitonic sort GBUF=2048, descending (key desc, idx asc via ~idx)
    for (int k2 = 2; k2 <= GBUF; k2 <<= 1) {
        for (int j = k2 >> 1; j > 0; j >>= 1) {
            __syncthreads();
            for (int idx = tid; idx < GBUF; idx += 1024) {
                int ixj = idx ^ j;
                if (ixj > idx) {
                    bool dir = ((idx & k2) == 0);
                    unsigned long long A = s_pairs[idx], Bv = s_pairs[ixj];
                    if ((A < Bv) == dir) { s_pairs[idx] = Bv; s_pairs[ixj] = A; }
                }
            }
        }
    }
    __syncthreads();

    // candidate data for top-1024 (fused gather of boxes/areas/classes)
    unsigned long long pr = s_pairs[tid];
    unsigned kk = (unsigned)(pr >> 32);
    unsigned ai = 0xFFFFFFFFu - (unsigned)(pr & 0xFFFFFFFFull);
    int t = b * KK + tid;
    float cx = 0.f, cy = 0.f, w = 0.f, h = 0.f, cls = 0.f;
    if (kk) {
        const float* p = pred + ((size_t)b * NN + (size_t)ai) * STRIDE;
        cx = p[0]; cy = p[1]; w = p[2]; h = p[3];
        cls = (float)g_cls[b * NN + ai];
    }
    float hw = __fmul_rn(w, 0.5f), hh = __fmul_rn(h, 0.5f);
    float x1 = __fsub_rn(cx, hw), y1 = __fsub_rn(cy, hh);
    float x2 = __fadd_rn(cx, hw), y2 = __fadd_rn(cy, hh);
    float off = __fmul_rn(cls, MAXWH);
    float ox1 = __fadd_rn(x1, off), oy1 = __fadd_rn(y1, off);
    float ox2 = __fadd_rn(x2, off), oy2 = __fadd_rn(y2, off);
    g_cbox [t] = make_float4(x1, y1, x2, y2);
    g_cobox[t] = make_float4(ox1, oy1, ox2, oy2);
    g_carea[t] = __fmul_rn(__fsub_rn(ox2, ox1), __fsub_rn(oy2, oy1));
    g_ccls [t] = cls;
    g_cconf[t] = kk ? __uint_as_float(kk) : -1.0f;
    if (tid == 0) g_nvalid[b] = min(cnt, KK);
}

// ---------------- K3: pairwise IoU bitmask, upper block-triangle, ballots --
__global__ void __launch_bounds__(256) iou_kernel() {
    int m = blockIdx.x % 136;
    int b = blockIdx.x / 136;
    int rb = 0, rem = m;
    #pragma unroll
    for (int i = 0; i < 16; ++i) {
        if (rem >= 16 - rb) { rem -= 16 - rb; rb++; } else break;
    }
    int cb = rb + rem;

    int tid  = threadIdx.x;
    int warp = tid >> 5, lane = tid & 31;

    __shared__ float4 s_box[64];
    __shared__ float  s_area[64];
    if (tid < 64) {
        int c = cb * 64 + tid;
        s_box[tid]  = g_cobox[b * KK + c];
        s_area[tid] = g_carea[b * KK + c];
    }
    __syncthreads();

    #pragma unroll
    for (int k = 0; k < 8; ++k) {
        int row = warp * 8 + k;                 // 0..63 within tile
        int r = rb * 64 + row;
        float4 rbx = g_cobox[b * KK + r];
        float  ra  = g_carea[b * KK + r];

        float4 o0 = s_box[lane];
        float4 o1 = s_box[lane + 32];

        float ix1 = fmaxf(rbx.x, o0.x), iy1 = fmaxf(rbx.y, o0.y);
        float ix2 = fminf(rbx.z, o0.z), iy2 = fminf(rbx.w, o0.w);
        float iw = fmaxf(__fsub_rn(ix2, ix1), 0.0f);
        float ih = fmaxf(__fsub_rn(iy2, iy1), 0.0f);
        float inter0 = __fmul_rn(iw, ih);

        ix1 = fmaxf(rbx.x, o1.x); iy1 = fmaxf(rbx.y, o1.y);
        ix2 = fminf(rbx.z, o1.z); iy2 = fminf(rbx.w, o1.w);
        iw = fmaxf(__fsub_rn(ix2, ix1), 0.0f);
        ih = fmaxf(__fsub_rn(iy2, iy1), 0.0f);
        float inter1 = __fmul_rn(iw, ih);

        bool hit0 = false, hit1 = false;
        if (inter0 > 0.0f) {
            float den0 = __fadd_rn(__fsub_rn(__fadd_rn(ra, s_area[lane]), inter0), 1e-9f);
            hit0 = __fdiv_rn(inter0, den0) > IOU_T;
        }
        if (inter1 > 0.0f) {
            float den1 = __fadd_rn(__fsub_rn(__fadd_rn(ra, s_area[lane + 32]), inter1), 1e-9f);
            hit1 = __fdiv_rn(inter1, den1) > IOU_T;
        }

        unsigned lo = __ballot_sync(0xffffffffu, hit0);
        unsigned hi = __ballot_sync(0xffffffffu, hit1);
        if (lane == 0)
            g_mask[((size_t)(b * KK + r)) * (KK/64) + cb] =
                ((unsigned long long)hi << 32) | (unsigned long long)lo;
    }
}

// ---------------- K4: suppression scan from SHARED-resident mask ----------
// Dynamic shared: full 1024x16 mask (128 KB) preloaded once; the 16-tile
// sequential scan then runs entirely out of shared memory.
__global__ void __launch_bounds__(1024) scan_output_kernel(float* __restrict__ out) {
    extern __shared__ unsigned long long s_mask[];   // [KK][16]
    int b = blockIdx.x, tid = threadIdx.x;
    const int NW = KK / 64;

    __shared__ unsigned long long s_remv[16];
    __shared__ unsigned long long s_keptAll[16];
    __shared__ short              s_outidx[MAXDET];

    // preload entire mask (coalesced; 16 ull per thread)
    const unsigned long long* gm = g_mask + (size_t)b * KK * NW;
    #pragma unroll
    for (int i = 0; i < 16; ++i)
        s_mask[tid + i * 1024] = gm[tid + i * 1024];

    int nvalid = g_nvalid[b];
    if (tid < 16) { s_remv[tid] = 0ull; s_keptAll[tid] = 0ull; }
    __syncthreads();

    for (int t = 0; t < 16; ++t) {
        if (tid == 0) {
            unsigned long long rem = s_remv[t], kept = 0ull;
            int base = t * 64;
            int lim = nvalid - base; if (lim > 64) lim = 64; if (lim < 0) lim = 0;
            for (int i = 0; i < lim; ++i) {
                if (!((rem >> i) & 1ull)) {
                    kept |= (1ull << i);
                    rem  |= s_mask[(base + i) * NW + t];
                }
            }
            s_keptAll[t] = kept;
        }
        __syncthreads();
        unsigned long long kept = s_keptAll[t];
        int i = tid >> 4, w = tid & 15;
        if (w > t && ((kept >> i) & 1ull))
            atomicOr(&s_remv[w], s_mask[(t * 64 + i) * NW + w]);
        __syncthreads();
    }

    // compaction: rank kept candidates (stable order = conf desc already)
    if (tid < MAXDET) s_outidx[tid] = -1;
    __syncthreads();
    {
        int r = tid, wr = r >> 6, br = r & 63;
        unsigned long long kw = s_keptAll[wr];
        if ((kw >> br) & 1ull) {
            int pos = 0;
            for (int w = 0; w < wr; ++w) pos += __popcll(s_keptAll[w]);
            pos += __popcll(kw & ((1ull << br) - 1ull));
            if (pos < MAXDET) s_outidx[pos] = (short)r;
        }
    }
    __syncthreads();

    float* outb = out + (size_t)b * MAXDET * 6;
    for (int row = tid; row < MAXDET; row += 1024) {
        int r = s_outidx[row];
        float v0, v1, v2, v3, v4, v5;
        if (r >= 0) {
            float4 bx = g_cbox[b * KK + r];
            v0 = bx.x; v1 = bx.y; v2 = bx.z; v3 = bx.w;
            v4 = g_cconf[b * KK + r];
            v5 = g_ccls [b * KK + r];
        } else {
            v0 = v1 = v2 = v3 = v4 = v5 = 0.0f;
        }
        float* o = outb + (size_t)row * 6;
        o[0] = v0; o[1] = v1; o[2] = v2; o[3] = v3; o[4] = v4; o[5] = v5;
    }
}

// ---------------- launch ---------------------------------------------------
extern "C" void kernel_launch(void* const* d_in, const int* in_sizes, int n_in,
                              void* d_out, int out_size) {
    const float* pred = (const float*)d_in[0];
    float* out = (float*)d_out;
    (void)in_sizes; (void)n_in; (void)out_size;

    const int SCAN_SMEM = KK * (KK / 64) * (int)sizeof(unsigned long long); // 128 KB
    static int attr_done = 0;
    if (!attr_done) {
        cudaFuncSetAttribute(scan_output_kernel,
                             cudaFuncAttributeMaxDynamicSharedMemorySize, SCAN_SMEM);
        attr_done = 1;
    }

    // K1: one warp per anchor, 8 warps/block (g_hist zero at entry:
    // zero-init at load, re-zeroed by select_sort each run)
    int nblocks1 = (BB * NN + 7) / 8;            // 50400
    score_kernel<<<nblocks1, 256>>>(pred);

    // K2: hist threshold + gather + bitonic sort + candidate data
    select_sort_kernel<<<BB, 1024>>>(pred);

    // K3: IoU mask tiles (upper block triangle)
    iou_kernel<<<BB * 136, 256>>>();

    // K4: suppression scan + output (mask in shared)
    scan_output_kernel<<<BB, 1024, SCAN_SMEM>>>(out);
}